// round 15
// baseline (speedup 1.0000x reference)
#include <cuda_runtime.h>
#include <cuda_bf16.h>

// Embedding gather: out[t, :] = W_E[tokens[t], :]
// tokens: int32 [32768]   (d_in[0])
// W_E:    float32 [50257, 768]  (d_in[1])
// out:    float32 [32768, 768]
//
// R14 -> R15: replay noise is ~±1us (R12 source re-ran 31.2 -> 32.8 with
// identical 26.0us kernel). Last untested cache-op: st.global.wt
// (write-through). Unlike .cs (evict-first but still ALLOCATES the line),
// .wt pushes the 96MB output stream through to the memory side without
// displacing W_E's ~74MB L2-resident read set — the strongest read/write
// L2 separation available. Load side unchanged: 8 tokens/CTA, batched __ldg
// float4 (MLP=8, 32 regs, occ ~75%).

#define D_MODEL 768
#define V4 (D_MODEL / 4)   // 192 float4 per row
#define U 8                // tokens per CTA

__global__ __launch_bounds__(V4) void embed_gather_kernel(
    const int* __restrict__ tokens,
    const float4* __restrict__ W,
    float4* __restrict__ out,
    int n_tok)
{
    const int col = threadIdx.x;
    const int t0  = blockIdx.x * U;

    if (t0 + U <= n_tok) {
        int rows[U];
#pragma unroll
        for (int u = 0; u < U; ++u)
            rows[u] = __ldg(tokens + t0 + u);       // independent, L2-hot

        float4 v[U];
#pragma unroll
        for (int u = 0; u < U; ++u)
            v[u] = __ldg(W + (size_t)rows[u] * V4 + col);   // 8 independent 128B/warp loads

#pragma unroll
        for (int u = 0; u < U; ++u) {
            float4* dst = out + (size_t)(t0 + u) * V4 + col;
            asm volatile(
                "st.global.wt.v4.f32 [%0], {%1, %2, %3, %4};"
                :: "l"(dst), "f"(v[u].x), "f"(v[u].y), "f"(v[u].z), "f"(v[u].w)
                : "memory");
        }
    } else {
        for (int t = t0; t < n_tok; ++t) {
            int row = __ldg(tokens + t);
            float4 v = __ldg(W + (size_t)row * V4 + col);
            float4* dst = out + (size_t)t * V4 + col;
            asm volatile(
                "st.global.wt.v4.f32 [%0], {%1, %2, %3, %4};"
                :: "l"(dst), "f"(v.x), "f"(v.y), "f"(v.z), "f"(v.w)
                : "memory");
        }
    }
}

extern "C" void kernel_launch(void* const* d_in, const int* in_sizes, int n_in,
                              void* d_out, int out_size)
{
    const int* tokens = (const int*)d_in[0];
    const float4* W   = (const float4*)d_in[1];
    float4* out       = (float4*)d_out;

    const int n_tok = in_sizes[0];   // 32768
    const int grid  = (n_tok + U - 1) / U;

    embed_gather_kernel<<<grid, V4>>>(tokens, W, out, n_tok);
}

// round 16
// speedup vs baseline: 1.0176x; 1.0176x over previous
#include <cuda_runtime.h>
#include <cuda_bf16.h>

// Embedding gather: out[t, :] = W_E[tokens[t], :]
// tokens: int32 [32768]   (d_in[0])
// W_E:    float32 [50257, 768]  (d_in[1])
// out:    float32 [32768, 768]
//
// FINAL (converged, R12 record config — dur_us 31.2, kernel 26.0us).
// Session-wide finding: register MLP, cp.async.bulk (one-shot + persistent),
// cp.async smem ring, L2 read policies, 256-bit LDG/STG, reg-budget, CTA
// pipelining, and all store cache-ops (default/.cs/.wt) converge at
// 25.5-26.2us kernel / ~4.7-4.95 TB/s on the ~123MB mixed random-read +
// streaming-write DRAM stream. That is the roofline for this pattern; the
// 96MB write stream is compulsory. Best measured combo:
//   - 8 tokens per 192-thread CTA; batched independent __ldg float4 row loads
//     (true MLP=8 at 32 regs, occ ~75%, perfectly coalesced 128B/warp)
//   - st.global.cs (evict-first) stores: best draws of the dur_us
//     distribution; protects W_E's L2 residency across warm graph replays.

#define D_MODEL 768
#define V4 (D_MODEL / 4)   // 192 float4 per row
#define U 8                // tokens per CTA

__global__ __launch_bounds__(V4) void embed_gather_kernel(
    const int* __restrict__ tokens,
    const float4* __restrict__ W,
    float4* __restrict__ out,
    int n_tok)
{
    const int col = threadIdx.x;
    const int t0  = blockIdx.x * U;

    if (t0 + U <= n_tok) {
        int rows[U];
#pragma unroll
        for (int u = 0; u < U; ++u)
            rows[u] = __ldg(tokens + t0 + u);       // independent, L2-hot

        float4 v[U];
#pragma unroll
        for (int u = 0; u < U; ++u)
            v[u] = __ldg(W + (size_t)rows[u] * V4 + col);   // 8 independent 128B/warp loads

#pragma unroll
        for (int u = 0; u < U; ++u) {
            float4* dst = out + (size_t)(t0 + u) * V4 + col;
            asm volatile(
                "st.global.cs.v4.f32 [%0], {%1, %2, %3, %4};"
                :: "l"(dst), "f"(v[u].x), "f"(v[u].y), "f"(v[u].z), "f"(v[u].w)
                : "memory");
        }
    } else {
        for (int t = t0; t < n_tok; ++t) {
            int row = __ldg(tokens + t);
            float4 v = __ldg(W + (size_t)row * V4 + col);
            float4* dst = out + (size_t)t * V4 + col;
            asm volatile(
                "st.global.cs.v4.f32 [%0], {%1, %2, %3, %4};"
                :: "l"(dst), "f"(v.x), "f"(v.y), "f"(v.z), "f"(v.w)
                : "memory");
        }
    }
}

extern "C" void kernel_launch(void* const* d_in, const int* in_sizes, int n_in,
                              void* d_out, int out_size)
{
    const int* tokens = (const int*)d_in[0];
    const float4* W   = (const float4*)d_in[1];
    float4* out       = (float4*)d_out;

    const int n_tok = in_sizes[0];   // 32768
    const int grid  = (n_tok + U - 1) / U;

    embed_gather_kernel<<<grid, V4>>>(tokens, W, out, n_tok);
}

// round 17
// speedup vs baseline: 1.0186x; 1.0010x over previous
#include <cuda_runtime.h>
#include <cuda_bf16.h>

// Embedding gather: out[t, :] = W_E[tokens[t], :]
// tokens: int32 [32768]   (d_in[0])
// W_E:    float32 [50257, 768]  (d_in[1])
// out:    float32 [32768, 768]
//
// R16 -> R17 (terminal micro-tweak on the converged record config):
// The 8 token-index loads are the serial prefix of every CTA. t0 = bid*8 is
// 32B-aligned, so fetch all 8 indices with TWO int4 loads instead of 8 scalar
// LDGs: shorter dependent prefix into the 8-deep row-load burst, 6 fewer
// L1tex wavefronts per CTA. Rest unchanged: 8 tokens per 192-thread CTA,
// batched __ldg float4 row loads (MLP=8), st.global.cs evict-first stores
// (protects W_E's L2 residency across warm graph replays).

#define D_MODEL 768
#define V4 (D_MODEL / 4)   // 192 float4 per row
#define U 8                // tokens per CTA

__global__ __launch_bounds__(V4) void embed_gather_kernel(
    const int* __restrict__ tokens,
    const float4* __restrict__ W,
    float4* __restrict__ out,
    int n_tok)
{
    const int col = threadIdx.x;
    const int t0  = blockIdx.x * U;

    if (t0 + U <= n_tok) {
        // 8 indices in two vector loads (tokens + t0 is 32B-aligned).
        const int4 ia = __ldg((const int4*)(tokens + t0));
        const int4 ib = __ldg((const int4*)(tokens + t0) + 1);
        int rows[U] = { ia.x, ia.y, ia.z, ia.w, ib.x, ib.y, ib.z, ib.w };

        float4 v[U];
#pragma unroll
        for (int u = 0; u < U; ++u)
            v[u] = __ldg(W + (size_t)rows[u] * V4 + col);   // 8 independent 128B/warp loads

#pragma unroll
        for (int u = 0; u < U; ++u) {
            float4* dst = out + (size_t)(t0 + u) * V4 + col;
            asm volatile(
                "st.global.cs.v4.f32 [%0], {%1, %2, %3, %4};"
                :: "l"(dst), "f"(v[u].x), "f"(v[u].y), "f"(v[u].z), "f"(v[u].w)
                : "memory");
        }
    } else {
        for (int t = t0; t < n_tok; ++t) {
            int row = __ldg(tokens + t);
            float4 v = __ldg(W + (size_t)row * V4 + col);
            float4* dst = out + (size_t)t * V4 + col;
            asm volatile(
                "st.global.cs.v4.f32 [%0], {%1, %2, %3, %4};"
                :: "l"(dst), "f"(v.x), "f"(v.y), "f"(v.z), "f"(v.w)
                : "memory");
        }
    }
}

extern "C" void kernel_launch(void* const* d_in, const int* in_sizes, int n_in,
                              void* d_out, int out_size)
{
    const int* tokens = (const int*)d_in[0];
    const float4* W   = (const float4*)d_in[1];
    float4* out       = (float4*)d_out;

    const int n_tok = in_sizes[0];   // 32768
    const int grid  = (n_tok + U - 1) / U;

    embed_gather_kernel<<<grid, V4>>>(tokens, W, out, n_tok);
}